// round 14
// baseline (speedup 1.0000x reference)
#include <cuda_runtime.h>
#include <math.h>

// RZ_50259707298063: y_re[s,b] = xr[s,b]*cos(phi_s) - xi[s,b]*sin(phi_s)
// phi_s = sum_i ( bit(s, nwires-1-i) ? +theta_i/2 : -theta_i/2 )
// Output = float32 real part (established round 7).
//
// R13: single fused kernel. Row index is warp-uniform (vpr >= 32), so lane 0
// computes the phase (12 broadcast angle loads + fast sincos) and shfl's it;
// cost ~1.5 instr/thread, hidden under the in-flight float4 loads. Default
// cache policy keeps the 24MB working set L2-resident across graph replays.

__global__ void __launch_bounds__(256) rz_fused_stream(
    const float4* __restrict__ xr,
    const float4* __restrict__ xi,
    const float* __restrict__ angle,
    int nwires, int log2_vpr, int nvec,
    float4* __restrict__ out)
{
    const int v = blockIdx.x * blockDim.x + threadIdx.x;
    if (v >= nvec) return;

    // Bulk loads first: in flight while the phase is computed.
    const float4 r  = xr[v];
    const float4 im = xi[v];

    const int s = v >> log2_vpr;           // warp-uniform (vpr >= 32)
    float cs = 0.0f, sn = 0.0f;
    if ((threadIdx.x & 31) == 0) {
        float phi = 0.0f;
        for (int i = 0; i < nwires; i++) {
            const float half = 0.5f * angle[i];   // L1-hit broadcast
            phi += ((s >> (nwires - 1 - i)) & 1) ? half : -half;
        }
        sincosf(phi, &sn, &cs);
    }
    cs = __shfl_sync(0xffffffffu, cs, 0);
    sn = __shfl_sync(0xffffffffu, sn, 0);

    float4 o;
    o.x = fmaf(r.x, cs, -im.x * sn);
    o.y = fmaf(r.y, cs, -im.y * sn);
    o.z = fmaf(r.z, cs, -im.z * sn);
    o.w = fmaf(r.w, cs, -im.w * sn);
    out[v] = o;
}

// Generic fallback (proven correct round 7).
__global__ void __launch_bounds__(256) rz_real_scalar(
    const float* __restrict__ xr,
    const float* __restrict__ xi,
    const float* __restrict__ angle,
    int nwires, int batch, long n,
    float* __restrict__ out)
{
    const long stride = (long)gridDim.x * blockDim.x;
    for (long e = (long)blockIdx.x * blockDim.x + threadIdx.x; e < n; e += stride) {
        const long s = e / batch;
        float phi = 0.0f;
        for (int i = 0; i < nwires; i++) {
            const float half = 0.5f * __ldg(&angle[i]);
            phi += (((s >> (nwires - 1 - i)) & 1L) != 0) ? half : -half;
        }
        float sn, cs;
        sincosf(phi, &sn, &cs);
        out[e] = fmaf(xr[e], cs, -xi[e] * sn);
    }
}

extern "C" void kernel_launch(void* const* d_in, const int* in_sizes, int n_in,
                              void* d_out, int out_size) {
    if (n_in < 3 || d_out == nullptr) return;

    // angle = smallest buffer; remaining two equal-size buffers, in index
    // order, are x_real then x_imag.
    int ai = 0;
    for (int i = 1; i < n_in; i++)
        if (in_sizes[i] < in_sizes[ai]) ai = i;

    const float* angle = (const float*)d_in[ai];
    const float* xr = nullptr;
    const float* xi = nullptr;
    long nelem = 0;
    for (int i = 0; i < n_in; i++) {
        if (i == ai) continue;
        if (xr == nullptr) { xr = (const float*)d_in[i]; nelem = in_sizes[i]; }
        else if (xi == nullptr && in_sizes[i] == (int)nelem)
            xi = (const float*)d_in[i];
    }
    if (!angle || !xr || !xi || nelem <= 0) return;

    int nwires = in_sizes[ai];
    if (nwires > 20) { nwires /= 4; nelem /= 4; }   // byte-count hedge
    if (nwires < 1 || nwires > 20) return;

    const long nstates = 1L << nwires;
    int batch = (int)(nelem / nstates);
    if (batch <= 0) batch = 1;

    // Output budget in floats (real part only).
    long n = nelem;
    if ((long)out_size < n) n = (long)out_size;

    // Fast path: vpr = batch/4 a power of two and >= 32 (warp-uniform row),
    // full coverage, sizes fit in int.
    const int vpr = batch / 4;
    int log2_vpr = 0;
    while ((1 << log2_vpr) < vpr && log2_vpr < 30) log2_vpr++;

    const bool fused_ok =
        (n == nelem) && (batch % 4 == 0) && ((1 << log2_vpr) == vpr) &&
        (vpr >= 32) && (n / 4 < (1L << 31));

    if (fused_ok) {
        const int nvec = (int)(n / 4);
        rz_fused_stream<<<(nvec + 255) / 256, 256>>>(
            (const float4*)xr, (const float4*)xi, angle,
            nwires, log2_vpr, nvec, (float4*)d_out);
    } else {
        rz_real_scalar<<<2048, 256>>>(xr, xi, angle, nwires, batch, n,
                                      (float*)d_out);
    }
}